// round 2
// baseline (speedup 1.0000x reference)
#include <cuda_runtime.h>
#include <cuda_bf16.h>

// Problem constants (fixed by the dataset)
#define NN      50000
#define EE      800000
#define ET      850000          // EE + NN self loops
#define IN_CH   128
#define HC      256
#define HEADS   4
#define NEG_SLOPE 0.2f
#define LN_EPS  1e-5f

// ---------------- device scratch (static, no runtime alloc) ----------------
__device__ float g_h[(size_t)NN * HC];       // 51.2 MB  h = x@W
__device__ float g_as[NN * HEADS];           // per-node att_src dot
__device__ float g_ad[NN * HEADS];           // per-node att_dst dot
__device__ int   g_deg[NN];
__device__ int   g_off[NN + 1];
__device__ int   g_cur[NN];
__device__ int   g_src[ET];                  // sorted-by-dst source node ids
__device__ float4 g_e[ET];                   // per sorted edge: 4-head logits

// ---------------- K1: init degree = 1 (self loop) ----------------
__global__ void k_init() {
    int i = blockIdx.x * blockDim.x + threadIdx.x;
    if (i < NN) g_deg[i] = 1;
}

// ---------------- K2: histogram of dst ----------------
__global__ void k_hist(const int* __restrict__ ei) {
    int i = blockIdx.x * blockDim.x + threadIdx.x;
    if (i < EE) {
        int dst = ei[EE + i];
        if (dst >= 0 && dst < NN) atomicAdd(&g_deg[dst], 1);
    }
}

// ---------------- K3: single-block exclusive scan ----------------
__global__ void k_scan() {
    __shared__ int s[1024];
    const int CH = (NN + 1023) / 1024;   // 49
    int t = threadIdx.x;
    int base = t * CH;
    int sum = 0;
    for (int j = 0; j < CH; j++) {
        int i = base + j;
        if (i < NN) sum += g_deg[i];
    }
    s[t] = sum;
    __syncthreads();
    // Hillis-Steele inclusive scan
    for (int o = 1; o < 1024; o <<= 1) {
        int v = (t >= o) ? s[t - o] : 0;
        __syncthreads();
        s[t] += v;
        __syncthreads();
    }
    int run = (t == 0) ? 0 : s[t - 1];
    for (int j = 0; j < CH; j++) {
        int i = base + j;
        if (i < NN) {
            g_off[i] = run;
            g_cur[i] = run;
            run += g_deg[i];
        }
    }
    if (t == 0) g_off[NN] = s[1023];
}

// ---------------- K4: GEMM  h[N,256] = x[N,128] @ W[128,256] ----------------
// 64x128 block tile, BK=16, 256 threads, 8x4 per-thread micro tile.
#define BM 64
#define BN 128
#define BK 16
#define APITCH 68

__global__ __launch_bounds__(256) void k_gemm(const float* __restrict__ x,
                                              const float* __restrict__ W) {
    __shared__ float As[BK * APITCH];
    __shared__ float Bs[BK * BN];
    int t  = threadIdx.x;
    int bm = blockIdx.x * BM;
    int bn = blockIdx.y * BN;
    int tx = t & 31;          // col group (tx*4)
    int ty = t >> 5;          // row group (ty*8)
    int lr = t >> 2;          // A-load row 0..63
    int lk = (t & 3) * 4;     // A-load k offset
    int wr = t >> 5;          // B-load k row 0..7
    int wc = (t & 31) * 4;    // B-load col

    float acc[8][4] = {};

    for (int kk = 0; kk < IN_CH; kk += BK) {
        float4 av = make_float4(0.f, 0.f, 0.f, 0.f);
        int row = bm + lr;
        if (row < NN) av = *(const float4*)(x + (size_t)row * IN_CH + kk + lk);
        As[(lk + 0) * APITCH + lr] = av.x;
        As[(lk + 1) * APITCH + lr] = av.y;
        As[(lk + 2) * APITCH + lr] = av.z;
        As[(lk + 3) * APITCH + lr] = av.w;
        #pragma unroll
        for (int r = 0; r < 2; r++) {
            int krow = wr + r * 8;
            *(float4*)(Bs + krow * BN + wc) =
                *(const float4*)(W + (size_t)(kk + krow) * HC + bn + wc);
        }
        __syncthreads();
        #pragma unroll
        for (int k = 0; k < BK; k++) {
            float a[8];
            *(float4*)(a)     = *(const float4*)(As + k * APITCH + ty * 8);
            *(float4*)(a + 4) = *(const float4*)(As + k * APITCH + ty * 8 + 4);
            float4 b = *(const float4*)(Bs + k * BN + tx * 4);
            #pragma unroll
            for (int i = 0; i < 8; i++) {
                acc[i][0] += a[i] * b.x;
                acc[i][1] += a[i] * b.y;
                acc[i][2] += a[i] * b.z;
                acc[i][3] += a[i] * b.w;
            }
        }
        __syncthreads();
    }
    #pragma unroll
    for (int i = 0; i < 8; i++) {
        int row = bm + ty * 8 + i;
        if (row < NN)
            *(float4*)(g_h + (size_t)row * HC + bn + tx * 4) = *(float4*)(acc[i]);
    }
}

// ---------------- K5: per-node attention halves a_s, a_d ----------------
// one warp per node; lane handles 8 contiguous channels (one head per 8 lanes)
__global__ void k_attn(const float* __restrict__ att_s,
                       const float* __restrict__ att_d) {
    int warp = threadIdx.x >> 5, lane = threadIdx.x & 31;
    int n = blockIdx.x * 8 + warp;
    if (n >= NN) return;
    const float4* hp = (const float4*)(g_h + (size_t)n * HC);
    float ps = 0.f, pd = 0.f;
    #pragma unroll
    for (int j = 0; j < 2; j++) {
        float4 v  = hp[lane * 2 + j];
        float4 s4 = ((const float4*)att_s)[lane * 2 + j];
        float4 d4 = ((const float4*)att_d)[lane * 2 + j];
        ps += v.x * s4.x + v.y * s4.y + v.z * s4.z + v.w * s4.w;
        pd += v.x * d4.x + v.y * d4.y + v.z * d4.z + v.w * d4.w;
    }
    #pragma unroll
    for (int o = 1; o < 8; o <<= 1) {
        ps += __shfl_xor_sync(0xffffffffu, ps, o);
        pd += __shfl_xor_sync(0xffffffffu, pd, o);
    }
    if ((lane & 7) == 0) {
        int h = lane >> 3;
        g_as[n * HEADS + h] = ps;
        g_ad[n * HEADS + h] = pd;
    }
}

// ---------------- K6: counting-sort scatter + per-edge logits ----------------
__global__ void k_scatter(const int* __restrict__ ei) {
    int i = blockIdx.x * blockDim.x + threadIdx.x;
    if (i >= ET) return;
    int src, dst;
    if (i < EE) { src = ei[i]; dst = ei[EE + i]; }
    else        { src = dst = i - EE; }
    if (src < 0 || src >= NN || dst < 0 || dst >= NN) return;
    int pos = atomicAdd(&g_cur[dst], 1);
    g_src[pos] = src;
    float4 as4 = *(const float4*)(g_as + src * HEADS);
    float4 ad4 = *(const float4*)(g_ad + dst * HEADS);
    float4 ev;
    float v;
    v = as4.x + ad4.x; ev.x = v > 0.f ? v : NEG_SLOPE * v;
    v = as4.y + ad4.y; ev.y = v > 0.f ? v : NEG_SLOPE * v;
    v = as4.z + ad4.z; ev.z = v > 0.f ? v : NEG_SLOPE * v;
    v = as4.w + ad4.w; ev.w = v > 0.f ? v : NEG_SLOPE * v;
    g_e[pos] = ev;
}

// ---------------- K7: per-dst softmax + aggregate + LN + ELU ----------------
// one 256-thread block per node; thread t owns channel t (head = t>>6)
__global__ __launch_bounds__(256) void k_agg(const float* __restrict__ bias,
                                             const float* __restrict__ gamma,
                                             const float* __restrict__ beta,
                                             float* __restrict__ out) {
    int n = blockIdx.x;
    int t = threadIdx.x;
    int lane = t & 31, warp = t >> 5;
    int start = g_off[n];
    int deg = g_off[n + 1] - start;

    __shared__ float s_m[4], s_inv[4];
    __shared__ float s_w[64 * 4];
    __shared__ int   s_src[64];
    __shared__ float red[8 * 4];

    const float* ef = (const float*)g_e;

    // --- phase 1: per-head max ---
    int sub = t >> 2;      // 0..63 edge lane
    int hd  = t & 3;       // head for stats phases
    float lm = -1e30f;
    for (int k = sub; k < deg; k += 64)
        lm = fmaxf(lm, ef[(size_t)(start + k) * 4 + hd]);
    lm = fmaxf(lm, __shfl_xor_sync(0xffffffffu, lm, 4));
    lm = fmaxf(lm, __shfl_xor_sync(0xffffffffu, lm, 8));
    lm = fmaxf(lm, __shfl_xor_sync(0xffffffffu, lm, 16));
    if (lane < 4) red[warp * 4 + lane] = lm;
    __syncthreads();
    if (t < 4) {
        float m = red[t];
        #pragma unroll
        for (int w = 1; w < 8; w++) m = fmaxf(m, red[w * 4 + t]);
        s_m[t] = m;
    }
    __syncthreads();

    // --- phase 2: per-head sum of exp ---
    float mh = s_m[hd];
    float ls = 0.f;
    for (int k = sub; k < deg; k += 64)
        ls += __expf(ef[(size_t)(start + k) * 4 + hd] - mh);
    ls += __shfl_xor_sync(0xffffffffu, ls, 4);
    ls += __shfl_xor_sync(0xffffffffu, ls, 8);
    ls += __shfl_xor_sync(0xffffffffu, ls, 16);
    __syncthreads();   // protect red[] reuse
    if (lane < 4) red[warp * 4 + lane] = ls;
    __syncthreads();
    if (t < 4) {
        float s = 0.f;
        #pragma unroll
        for (int w = 0; w < 8; w++) s += red[w * 4 + t];
        s_inv[t] = 1.f / (s + 1e-16f);
    }
    __syncthreads();

    // --- phase 3: weighted accumulate over chunks of 64 edges ---
    float acc = 0.f;
    int head = t >> 6;
    for (int c0 = 0; c0 < deg; c0 += 64) {
        int cn = min(64, deg - c0);
        if (sub < cn)
            s_w[sub * 4 + hd] =
                __expf(ef[(size_t)(start + c0 + sub) * 4 + hd] - s_m[hd]) * s_inv[hd];
        if (t < cn) s_src[t] = g_src[start + c0 + t];
        __syncthreads();
        #pragma unroll 4
        for (int k = 0; k < cn; k++) {
            int src = s_src[k];
            float w = s_w[k * 4 + head];
            acc += w * g_h[(size_t)src * HC + t];
        }
        __syncthreads();
    }

    // --- phase 4: bias + LayerNorm + ELU ---
    acc += bias[t];
    float v = acc, v2 = acc * acc;
    #pragma unroll
    for (int o = 16; o; o >>= 1) {
        v  += __shfl_xor_sync(0xffffffffu, v,  o);
        v2 += __shfl_xor_sync(0xffffffffu, v2, o);
    }
    __shared__ float rs[8], rs2[8];
    __shared__ float s_mu, s_r;
    if (lane == 0) { rs[warp] = v; rs2[warp] = v2; }
    __syncthreads();
    if (t == 0) {
        float S = 0.f, S2 = 0.f;
        #pragma unroll
        for (int w = 0; w < 8; w++) { S += rs[w]; S2 += rs2[w]; }
        float mu = S / (float)HC;
        float var = S2 / (float)HC - mu * mu;
        s_mu = mu;
        s_r = rsqrtf(var + LN_EPS);
    }
    __syncthreads();
    float nv = (acc - s_mu) * s_r * gamma[t] + beta[t];
    out[(size_t)n * HC + t] = nv > 0.f ? nv : (__expf(nv) - 1.f);
}

// ---------------- launch ----------------
extern "C" void kernel_launch(void* const* d_in, const int* in_sizes, int n_in,
                              void* d_out, int out_size) {
    const float* x     = (const float*)d_in[0];
    const int*   ei    = (const int*)d_in[1];
    const float* W     = (const float*)d_in[2];
    const float* att_s = (const float*)d_in[3];
    const float* att_d = (const float*)d_in[4];
    const float* bias  = (const float*)d_in[5];
    const float* gamma = (const float*)d_in[6];
    const float* beta  = (const float*)d_in[7];
    float*       out   = (float*)d_out;

    k_init<<<(NN + 255) / 256, 256>>>();
    k_hist<<<(EE + 255) / 256, 256>>>(ei);
    k_scan<<<1, 1024>>>();
    dim3 gg((NN + BM - 1) / BM, HC / BN);
    k_gemm<<<gg, 256>>>(x, W);
    k_attn<<<(NN + 7) / 8, 256>>>(att_s, att_d);
    k_scatter<<<(ET + 255) / 256, 256>>>(ei);
    k_agg<<<NN, 256>>>(bias, gamma, beta, out);
}

// round 3
// speedup vs baseline: 1.0102x; 1.0102x over previous
#include <cuda_runtime.h>
#include <cuda_bf16.h>

// Problem constants (fixed by the dataset)
#define NN      50000
#define EE      800000
#define ET      850000          // EE + NN self loops
#define IN_CH   128
#define HC      256
#define HEADS   4
#define NEG_SLOPE 0.2f
#define LN_EPS  1e-5f

// ---------------- device scratch (static, no runtime alloc) ----------------
__device__ float g_h[(size_t)NN * HC];       // 51.2 MB  h = x@W
__device__ float g_as[NN * HEADS];           // per-node att_src dot
__device__ float g_ad[NN * HEADS];           // per-node att_dst dot
__device__ int   g_deg[NN];
__device__ int   g_off[NN + 1];
__device__ int   g_cur[NN];
__device__ int   g_src[ET];                  // sorted-by-dst source node ids
__device__ float4 g_e[ET];                   // per sorted edge: exp(leakyrelu) per head

// ---------------- K1: init degree = 1 (self loop) ----------------
__global__ void k_init() {
    int i = blockIdx.x * blockDim.x + threadIdx.x;
    if (i < NN) g_deg[i] = 1;
}

// ---------------- K2: histogram of dst ----------------
__global__ void k_hist(const int* __restrict__ ei) {
    int i = blockIdx.x * blockDim.x + threadIdx.x;
    if (i < EE) {
        int dst = ei[EE + i];
        if (dst >= 0 && dst < NN) atomicAdd(&g_deg[dst], 1);
    }
}

// ---------------- K3: single-block exclusive scan ----------------
__global__ void k_scan() {
    __shared__ int s[1024];
    const int CH = (NN + 1023) / 1024;   // 49
    int t = threadIdx.x;
    int base = t * CH;
    int sum = 0;
    for (int j = 0; j < CH; j++) {
        int i = base + j;
        if (i < NN) sum += g_deg[i];
    }
    s[t] = sum;
    __syncthreads();
    for (int o = 1; o < 1024; o <<= 1) {
        int v = (t >= o) ? s[t - o] : 0;
        __syncthreads();
        s[t] += v;
        __syncthreads();
    }
    int run = (t == 0) ? 0 : s[t - 1];
    for (int j = 0; j < CH; j++) {
        int i = base + j;
        if (i < NN) {
            g_off[i] = run;
            g_cur[i] = run;
            run += g_deg[i];
        }
    }
    if (t == 0) g_off[NN] = s[1023];
}

// ---------------- K4: GEMM h = x@W + fused per-node attention dots ----------
// 64x256 block tile (full row), BK=16, 256 threads, 8x8 micro tile.
#define BM 64
#define BK 16
#define APITCH 68

__global__ __launch_bounds__(256) void k_gemm(const float* __restrict__ x,
                                              const float* __restrict__ W,
                                              const float* __restrict__ att_s,
                                              const float* __restrict__ att_d) {
    __shared__ float As[BK * APITCH];      // transposed: As[k][row]
    __shared__ float Bs[BK * HC];          // Bs[k][col]
    int t  = threadIdx.x;
    int bm = blockIdx.x * BM;
    int tx = t & 31;          // col group: cols tx*8 .. tx*8+7
    int ty = t >> 5;          // row group: rows ty*8 .. ty*8+7
    int lr = t >> 2;          // A-load row 0..63
    int lk = (t & 3) * 4;     // A-load k offset

    float acc[8][8] = {};

    for (int kk = 0; kk < IN_CH; kk += BK) {
        // load A tile (transposed into As)
        float4 av = make_float4(0.f, 0.f, 0.f, 0.f);
        int row = bm + lr;
        if (row < NN) av = *(const float4*)(x + (size_t)row * IN_CH + kk + lk);
        As[(lk + 0) * APITCH + lr] = av.x;
        As[(lk + 1) * APITCH + lr] = av.y;
        As[(lk + 2) * APITCH + lr] = av.z;
        As[(lk + 3) * APITCH + lr] = av.w;
        // load B tile: 16x256 = 1024 float4, 4 per thread
        #pragma unroll
        for (int r = 0; r < 4; r++) {
            int idx = t + 256 * r;
            int krow = idx >> 6;
            int col = (idx & 63) * 4;
            *(float4*)(Bs + krow * HC + col) =
                *(const float4*)(W + (size_t)(kk + krow) * HC + col);
        }
        __syncthreads();
        #pragma unroll
        for (int k = 0; k < BK; k++) {
            float a[8], b[8];
            *(float4*)(a)     = *(const float4*)(As + k * APITCH + ty * 8);
            *(float4*)(a + 4) = *(const float4*)(As + k * APITCH + ty * 8 + 4);
            *(float4*)(b)     = *(const float4*)(Bs + k * HC + tx * 8);
            *(float4*)(b + 4) = *(const float4*)(Bs + k * HC + tx * 8 + 4);
            #pragma unroll
            for (int i = 0; i < 8; i++)
                #pragma unroll
                for (int j = 0; j < 8; j++)
                    acc[i][j] += a[i] * b[j];
        }
        __syncthreads();
    }

    // epilogue: store h + fused attention dots
    int head = tx >> 3;                       // cols tx*8 all in this head
    const float4* sa = (const float4*)(att_s + head * 64 + (tx & 7) * 8);
    const float4* da = (const float4*)(att_d + head * 64 + (tx & 7) * 8);
    float4 s0 = sa[0], s1 = sa[1];
    float4 d0 = da[0], d1 = da[1];

    #pragma unroll
    for (int i = 0; i < 8; i++) {
        int row = bm + ty * 8 + i;
        if (row < NN) {
            *(float4*)(g_h + (size_t)row * HC + tx * 8)     = *(float4*)(acc[i]);
            *(float4*)(g_h + (size_t)row * HC + tx * 8 + 4) = *(float4*)(acc[i] + 4);
        }
        float ps = acc[i][0] * s0.x + acc[i][1] * s0.y + acc[i][2] * s0.z + acc[i][3] * s0.w
                 + acc[i][4] * s1.x + acc[i][5] * s1.y + acc[i][6] * s1.z + acc[i][7] * s1.w;
        float pd = acc[i][0] * d0.x + acc[i][1] * d0.y + acc[i][2] * d0.z + acc[i][3] * d0.w
                 + acc[i][4] * d1.x + acc[i][5] * d1.y + acc[i][6] * d1.z + acc[i][7] * d1.w;
        ps += __shfl_xor_sync(0xffffffffu, ps, 1);
        ps += __shfl_xor_sync(0xffffffffu, ps, 2);
        ps += __shfl_xor_sync(0xffffffffu, ps, 4);
        pd += __shfl_xor_sync(0xffffffffu, pd, 1);
        pd += __shfl_xor_sync(0xffffffffu, pd, 2);
        pd += __shfl_xor_sync(0xffffffffu, pd, 4);
        if ((tx & 7) == 0 && row < NN) {
            g_as[row * HEADS + head] = ps;
            g_ad[row * HEADS + head] = pd;
        }
    }
}

// ---------------- K6: counting-sort scatter + per-edge exp-logits ----------
__global__ void k_scatter(const int* __restrict__ ei) {
    int i = blockIdx.x * blockDim.x + threadIdx.x;
    if (i >= ET) return;
    int src, dst;
    if (i < EE) { src = ei[i]; dst = ei[EE + i]; }
    else        { src = dst = i - EE; }
    if (src < 0 || src >= NN || dst < 0 || dst >= NN) return;
    int pos = atomicAdd(&g_cur[dst], 1);
    g_src[pos] = src;
    float4 as4 = *(const float4*)(g_as + src * HEADS);
    float4 ad4 = *(const float4*)(g_ad + dst * HEADS);
    float4 ev;
    float v;
    v = as4.x + ad4.x; ev.x = __expf(v > 0.f ? v : NEG_SLOPE * v);
    v = as4.y + ad4.y; ev.y = __expf(v > 0.f ? v : NEG_SLOPE * v);
    v = as4.z + ad4.z; ev.z = __expf(v > 0.f ? v : NEG_SLOPE * v);
    v = as4.w + ad4.w; ev.w = __expf(v > 0.f ? v : NEG_SLOPE * v);
    g_e[pos] = ev;
}

// ---------------- K7: per-dst softmax-aggregate + LN + ELU ------------------
// one 256-thread block per node; 4 edge-subgroups x 64 channel-groups(float4)
__global__ __launch_bounds__(256) void k_agg(const float* __restrict__ bias,
                                             const float* __restrict__ gamma,
                                             const float* __restrict__ beta,
                                             float* __restrict__ out) {
    int n = blockIdx.x;
    int t = threadIdx.x;
    int lane = t & 31, warp = t >> 5;
    int start = g_off[n];
    int deg = g_off[n + 1] - start;

    __shared__ float4 s_w[64];
    __shared__ int    s_src[64];
    __shared__ float4 s_red[256];
    __shared__ float4 s_part[8];
    __shared__ float4 s_inv4;
    __shared__ float  s_s[2], s_s2[2];

    // --- phase A: per-head sum of exp ---
    float4 ls = make_float4(0.f, 0.f, 0.f, 0.f);
    for (int k = t; k < deg; k += 256) {
        float4 e = g_e[start + k];
        ls.x += e.x; ls.y += e.y; ls.z += e.z; ls.w += e.w;
    }
    #pragma unroll
    for (int o = 16; o; o >>= 1) {
        ls.x += __shfl_xor_sync(0xffffffffu, ls.x, o);
        ls.y += __shfl_xor_sync(0xffffffffu, ls.y, o);
        ls.z += __shfl_xor_sync(0xffffffffu, ls.z, o);
        ls.w += __shfl_xor_sync(0xffffffffu, ls.w, o);
    }
    if (lane == 0) s_part[warp] = ls;
    __syncthreads();
    if (t == 0) {
        float4 s = make_float4(0.f, 0.f, 0.f, 0.f);
        #pragma unroll
        for (int w = 0; w < 8; w++) {
            float4 p = s_part[w];
            s.x += p.x; s.y += p.y; s.z += p.z; s.w += p.w;
        }
        s_inv4 = make_float4(1.f / (s.x + 1e-16f), 1.f / (s.y + 1e-16f),
                             1.f / (s.z + 1e-16f), 1.f / (s.w + 1e-16f));
    }
    __syncthreads();
    float4 inv = s_inv4;

    // --- phase B: weighted accumulate, 4 edges in flight ---
    int eg = t >> 6;          // edge subgroup 0..3
    int cg = t & 63;          // channel group (4 channels at cg*4)
    int head = cg >> 4;
    float4 acc = make_float4(0.f, 0.f, 0.f, 0.f);
    for (int c0 = 0; c0 < deg; c0 += 64) {
        int cn = min(64, deg - c0);
        if (t < cn) {
            s_src[t] = g_src[start + c0 + t];
            float4 e = g_e[start + c0 + t];
            s_w[t] = make_float4(e.x * inv.x, e.y * inv.y, e.z * inv.z, e.w * inv.w);
        }
        __syncthreads();
        const float* wv = (const float*)s_w;
        #pragma unroll 2
        for (int k = eg; k < cn; k += 4) {
            int src = s_src[k];
            float w = wv[k * 4 + head];
            float4 hv = *(const float4*)(g_h + (size_t)src * HC + cg * 4);
            acc.x += w * hv.x; acc.y += w * hv.y;
            acc.z += w * hv.z; acc.w += w * hv.w;
        }
        __syncthreads();
    }

    // --- reduce 4 subgroups ---
    s_red[t] = acc;
    __syncthreads();

    float ss = 0.f, ss2 = 0.f;
    float4 v = make_float4(0.f, 0.f, 0.f, 0.f);
    if (t < 64) {
        v = s_red[t];
        float4 a = s_red[64 + t], b = s_red[128 + t], c = s_red[192 + t];
        v.x += a.x + b.x + c.x; v.y += a.y + b.y + c.y;
        v.z += a.z + b.z + c.z; v.w += a.w + b.w + c.w;
        float4 bi = ((const float4*)bias)[t];
        v.x += bi.x; v.y += bi.y; v.z += bi.z; v.w += bi.w;
        ss = v.x + v.y + v.z + v.w;
        ss2 = v.x * v.x + v.y * v.y + v.z * v.z + v.w * v.w;
    }
    #pragma unroll
    for (int o = 16; o; o >>= 1) {
        ss  += __shfl_xor_sync(0xffffffffu, ss,  o);
        ss2 += __shfl_xor_sync(0xffffffffu, ss2, o);
    }
    if (t < 64 && lane == 0) { s_s[warp] = ss; s_s2[warp] = ss2; }
    __syncthreads();
    if (t < 64) {
        float S = s_s[0] + s_s[1], S2 = s_s2[0] + s_s2[1];
        float mu = S * (1.f / (float)HC);
        float var = S2 * (1.f / (float)HC) - mu * mu;
        float r = rsqrtf(var + LN_EPS);
        float4 g = ((const float4*)gamma)[t];
        float4 be = ((const float4*)beta)[t];
        float4 o4;
        o4.x = (v.x - mu) * r * g.x + be.x;
        o4.y = (v.y - mu) * r * g.y + be.y;
        o4.z = (v.z - mu) * r * g.z + be.z;
        o4.w = (v.w - mu) * r * g.w + be.w;
        o4.x = o4.x > 0.f ? o4.x : (__expf(o4.x) - 1.f);
        o4.y = o4.y > 0.f ? o4.y : (__expf(o4.y) - 1.f);
        o4.z = o4.z > 0.f ? o4.z : (__expf(o4.z) - 1.f);
        o4.w = o4.w > 0.f ? o4.w : (__expf(o4.w) - 1.f);
        ((float4*)out)[(size_t)n * 64 + t] = o4;
    }
}

// ---------------- launch ----------------
extern "C" void kernel_launch(void* const* d_in, const int* in_sizes, int n_in,
                              void* d_out, int out_size) {
    const float* x     = (const float*)d_in[0];
    const int*   ei    = (const int*)d_in[1];
    const float* W     = (const float*)d_in[2];
    const float* att_s = (const float*)d_in[3];
    const float* att_d = (const float*)d_in[4];
    const float* bias  = (const float*)d_in[5];
    const float* gamma = (const float*)d_in[6];
    const float* beta  = (const float*)d_in[7];
    float*       out   = (float*)d_out;

    k_init<<<(NN + 255) / 256, 256>>>();
    k_hist<<<(EE + 255) / 256, 256>>>(ei);
    k_scan<<<1, 1024>>>();
    k_gemm<<<(NN + BM - 1) / BM, 256>>>(x, W, att_s, att_d);
    k_scatter<<<(ET + 255) / 256, 256>>>(ei);
    k_agg<<<NN, 256>>>(bias, gamma, beta, out);
}

// round 4
// speedup vs baseline: 1.5063x; 1.4911x over previous
#include <cuda_runtime.h>
#include <cuda_bf16.h>

// Problem constants (fixed by the dataset)
#define NN      50000
#define EE      800000
#define ET      850000          // EE + NN self loops
#define IN_CH   128
#define HC      256
#define HEADS   4
#define NEG_SLOPE 0.2f
#define LN_EPS  1e-5f

// packed fp32x2 helpers (FFMA2 path — 2x fp32 throughput on sm_103a)
#define FMA2(d, a, b, c) \
    asm("fma.rn.f32x2 %0, %1, %2, %3;" : "=l"(d) : "l"(a), "l"(b), "l"(c))
#define PACK2(d, x, y) \
    asm("mov.b64 %0, {%1, %2};" : "=l"(d) : "r"(__float_as_uint(x)), "r"(__float_as_uint(y)))
#define UNPACK2(x, y, d) \
    asm("mov.b64 {%0, %1}, %2;" : "=r"(x), "=r"(y) : "l"(d))

// ---------------- device scratch (static, no runtime alloc) ----------------
__device__ float g_h[(size_t)NN * HC];       // 51.2 MB  h = x@W
__device__ float g_as[NN * HEADS];           // per-node att_src dot
__device__ float g_ad[NN * HEADS];           // per-node att_dst dot
__device__ int   g_deg[NN];
__device__ int   g_off[NN + 1];
__device__ int   g_cur[NN];
__device__ int   g_src[ET];                  // sorted-by-dst source node ids
__device__ float4 g_e[ET];                   // per sorted edge: exp(leakyrelu) per head

// ---------------- K1: init degree = 1 (self loop) ----------------
__global__ void k_init() {
    int i = blockIdx.x * blockDim.x + threadIdx.x;
    if (i < NN) g_deg[i] = 1;
}

// ---------------- K2: histogram of dst ----------------
__global__ void k_hist(const int* __restrict__ ei) {
    int i = blockIdx.x * blockDim.x + threadIdx.x;
    if (i < EE) {
        int dst = ei[EE + i];
        if (dst >= 0 && dst < NN) atomicAdd(&g_deg[dst], 1);
    }
}

// ---------------- K3: single-block exclusive scan ----------------
__global__ void k_scan() {
    __shared__ int s[1024];
    const int CH = (NN + 1023) / 1024;   // 49
    int t = threadIdx.x;
    int base = t * CH;
    int sum = 0;
    for (int j = 0; j < CH; j++) {
        int i = base + j;
        if (i < NN) sum += g_deg[i];
    }
    s[t] = sum;
    __syncthreads();
    for (int o = 1; o < 1024; o <<= 1) {
        int v = (t >= o) ? s[t - o] : 0;
        __syncthreads();
        s[t] += v;
        __syncthreads();
    }
    int run = (t == 0) ? 0 : s[t - 1];
    for (int j = 0; j < CH; j++) {
        int i = base + j;
        if (i < NN) {
            g_off[i] = run;
            g_cur[i] = run;
            run += g_deg[i];
        }
    }
    if (t == 0) g_off[NN] = s[1023];
}

// ---------------- K4: GEMM h = x@W (packed f32x2) + fused attention dots ----
// 64x128 block tile, BK=16, 256 threads, 8x4 micro tile as 8x2 packed pairs.
#define BM 64
#define BN 128
#define BK 16
#define APITCH 68

__global__ __launch_bounds__(256) void k_gemm(const float* __restrict__ x,
                                              const float* __restrict__ W,
                                              const float* __restrict__ att_s,
                                              const float* __restrict__ att_d) {
    __shared__ float As[BK * APITCH];      // transposed: As[k][row]
    __shared__ float Bs[BK * BN];          // Bs[k][col]
    int t  = threadIdx.x;
    int bm = blockIdx.x * BM;
    int bn = blockIdx.y * BN;
    int tx = t & 31;          // col group (cols bn + tx*4 .. +3)
    int ty = t >> 5;          // row group (rows ty*8 .. ty*8+7)
    int lr = t >> 2;          // A-load row 0..63
    int lk = (t & 3) * 4;     // A-load k offset
    int wr = t >> 5;          // B-load k row 0..7
    int wc = (t & 31) * 4;    // B-load col

    unsigned long long acc[8][2] = {};     // packed fp32 pairs

    for (int kk = 0; kk < IN_CH; kk += BK) {
        float4 av = make_float4(0.f, 0.f, 0.f, 0.f);
        int row = bm + lr;
        if (row < NN) av = *(const float4*)(x + (size_t)row * IN_CH + kk + lk);
        As[(lk + 0) * APITCH + lr] = av.x;
        As[(lk + 1) * APITCH + lr] = av.y;
        As[(lk + 2) * APITCH + lr] = av.z;
        As[(lk + 3) * APITCH + lr] = av.w;
        #pragma unroll
        for (int r = 0; r < 2; r++) {
            int krow = wr + r * 8;
            *(float4*)(Bs + krow * BN + wc) =
                *(const float4*)(W + (size_t)(kk + krow) * HC + bn + wc);
        }
        __syncthreads();
        #pragma unroll
        for (int k = 0; k < BK; k++) {
            float a[8];
            *(float4*)(a)     = *(const float4*)(As + k * APITCH + ty * 8);
            *(float4*)(a + 4) = *(const float4*)(As + k * APITCH + ty * 8 + 4);
            float4 b = *(const float4*)(Bs + k * BN + tx * 4);
            unsigned long long bp0, bp1;
            PACK2(bp0, b.x, b.y);
            PACK2(bp1, b.z, b.w);
            #pragma unroll
            for (int i = 0; i < 8; i++) {
                unsigned long long a2;
                PACK2(a2, a[i], a[i]);
                FMA2(acc[i][0], a2, bp0, acc[i][0]);
                FMA2(acc[i][1], a2, bp1, acc[i][1]);
            }
        }
        __syncthreads();
    }

    // epilogue: unpack, store h, fused attention dots
    int head = (bn >> 6) + (tx >> 4);          // 64 cols per head
    int coff = (tx & 15) * 4;                  // channel offset within head
    float4 sa = *(const float4*)(att_s + head * 64 + coff);
    float4 da = *(const float4*)(att_d + head * 64 + coff);

    #pragma unroll
    for (int i = 0; i < 8; i++) {
        unsigned int u0, u1, u2, u3;
        UNPACK2(u0, u1, acc[i][0]);
        UNPACK2(u2, u3, acc[i][1]);
        float4 c = make_float4(__uint_as_float(u0), __uint_as_float(u1),
                               __uint_as_float(u2), __uint_as_float(u3));
        int row = bm + ty * 8 + i;
        if (row < NN)
            *(float4*)(g_h + (size_t)row * HC + bn + tx * 4) = c;
        float ps = c.x * sa.x + c.y * sa.y + c.z * sa.z + c.w * sa.w;
        float pd = c.x * da.x + c.y * da.y + c.z * da.z + c.w * da.w;
        #pragma unroll
        for (int o = 1; o < 16; o <<= 1) {
            ps += __shfl_xor_sync(0xffffffffu, ps, o);
            pd += __shfl_xor_sync(0xffffffffu, pd, o);
        }
        if ((tx & 15) == 0 && row < NN) {
            g_as[row * HEADS + head] = ps;
            g_ad[row * HEADS + head] = pd;
        }
    }
}

// ---------------- K6: counting-sort scatter + per-edge exp-logits ----------
__global__ void k_scatter(const int* __restrict__ ei) {
    int i = blockIdx.x * blockDim.x + threadIdx.x;
    if (i >= ET) return;
    int src, dst;
    if (i < EE) { src = ei[i]; dst = ei[EE + i]; }
    else        { src = dst = i - EE; }
    if (src < 0 || src >= NN || dst < 0 || dst >= NN) return;
    int pos = atomicAdd(&g_cur[dst], 1);
    g_src[pos] = src;
    float4 as4 = *(const float4*)(g_as + src * HEADS);
    float4 ad4 = *(const float4*)(g_ad + dst * HEADS);
    float4 ev;
    float v;
    v = as4.x + ad4.x; ev.x = __expf(v > 0.f ? v : NEG_SLOPE * v);
    v = as4.y + ad4.y; ev.y = __expf(v > 0.f ? v : NEG_SLOPE * v);
    v = as4.z + ad4.z; ev.z = __expf(v > 0.f ? v : NEG_SLOPE * v);
    v = as4.w + ad4.w; ev.w = __expf(v > 0.f ? v : NEG_SLOPE * v);
    g_e[pos] = ev;
}

// ---------------- K7: warp-per-node softmax-aggregate + LN + ELU ------------
// lane owns 8 channels (head = lane>>3). Single pass, no block barriers.
__global__ __launch_bounds__(256) void k_agg(const float* __restrict__ bias,
                                             const float* __restrict__ gamma,
                                             const float* __restrict__ beta,
                                             float* __restrict__ out) {
    int lane = threadIdx.x & 31;
    int n = blockIdx.x * 8 + (threadIdx.x >> 5);
    if (n >= NN) return;
    int start = g_off[n];
    int end   = g_off[n + 1];
    int head  = lane >> 3;
    int cb    = lane * 8;                    // first channel this lane owns
    const float* ef = (const float*)g_e;

    float4 acc0 = make_float4(0.f, 0.f, 0.f, 0.f);
    float4 acc1 = make_float4(0.f, 0.f, 0.f, 0.f);
    float wsum = 0.f;

    for (int c = start; c < end; c += 32) {
        int sv = 0;
        if (c + lane < end) sv = g_src[c + lane];
        int cn = min(32, end - c);
        #pragma unroll 4
        for (int j = 0; j < cn; j++) {
            int src = __shfl_sync(0xffffffffu, sv, j);
            float w = ef[(size_t)(c + j) * 4 + head];
            wsum += w;
            const float4* hp = (const float4*)(g_h + (size_t)src * HC + cb);
            float4 h0 = hp[0], h1 = hp[1];
            acc0.x += w * h0.x; acc0.y += w * h0.y;
            acc0.z += w * h0.z; acc0.w += w * h0.w;
            acc1.x += w * h1.x; acc1.y += w * h1.y;
            acc1.z += w * h1.z; acc1.w += w * h1.w;
        }
    }

    float inv = 1.f / (wsum + 1e-16f);
    float4 b0 = ((const float4*)bias)[lane * 2];
    float4 b1 = ((const float4*)bias)[lane * 2 + 1];
    acc0.x = acc0.x * inv + b0.x; acc0.y = acc0.y * inv + b0.y;
    acc0.z = acc0.z * inv + b0.z; acc0.w = acc0.w * inv + b0.w;
    acc1.x = acc1.x * inv + b1.x; acc1.y = acc1.y * inv + b1.y;
    acc1.z = acc1.z * inv + b1.z; acc1.w = acc1.w * inv + b1.w;

    // LayerNorm over all 256 channels (warp reduce)
    float ss  = acc0.x + acc0.y + acc0.z + acc0.w + acc1.x + acc1.y + acc1.z + acc1.w;
    float ss2 = acc0.x * acc0.x + acc0.y * acc0.y + acc0.z * acc0.z + acc0.w * acc0.w
              + acc1.x * acc1.x + acc1.y * acc1.y + acc1.z * acc1.z + acc1.w * acc1.w;
    #pragma unroll
    for (int o = 16; o; o >>= 1) {
        ss  += __shfl_xor_sync(0xffffffffu, ss,  o);
        ss2 += __shfl_xor_sync(0xffffffffu, ss2, o);
    }
    float mu  = ss * (1.f / (float)HC);
    float var = ss2 * (1.f / (float)HC) - mu * mu;
    float r = rsqrtf(var + LN_EPS);

    float4 g0 = ((const float4*)gamma)[lane * 2];
    float4 g1 = ((const float4*)gamma)[lane * 2 + 1];
    float4 e0 = ((const float4*)beta)[lane * 2];
    float4 e1 = ((const float4*)beta)[lane * 2 + 1];
    float4 o0, o1;
    o0.x = (acc0.x - mu) * r * g0.x + e0.x;
    o0.y = (acc0.y - mu) * r * g0.y + e0.y;
    o0.z = (acc0.z - mu) * r * g0.z + e0.z;
    o0.w = (acc0.w - mu) * r * g0.w + e0.w;
    o1.x = (acc1.x - mu) * r * g1.x + e1.x;
    o1.y = (acc1.y - mu) * r * g1.y + e1.y;
    o1.z = (acc1.z - mu) * r * g1.z + e1.z;
    o1.w = (acc1.w - mu) * r * g1.w + e1.w;
    o0.x = o0.x > 0.f ? o0.x : (__expf(o0.x) - 1.f);
    o0.y = o0.y > 0.f ? o0.y : (__expf(o0.y) - 1.f);
    o0.z = o0.z > 0.f ? o0.z : (__expf(o0.z) - 1.f);
    o0.w = o0.w > 0.f ? o0.w : (__expf(o0.w) - 1.f);
    o1.x = o1.x > 0.f ? o1.x : (__expf(o1.x) - 1.f);
    o1.y = o1.y > 0.f ? o1.y : (__expf(o1.y) - 1.f);
    o1.z = o1.z > 0.f ? o1.z : (__expf(o1.z) - 1.f);
    o1.w = o1.w > 0.f ? o1.w : (__expf(o1.w) - 1.f);
    ((float4*)out)[(size_t)n * 64 + lane * 2]     = o0;
    ((float4*)out)[(size_t)n * 64 + lane * 2 + 1] = o1;
}

// ---------------- launch ----------------
extern "C" void kernel_launch(void* const* d_in, const int* in_sizes, int n_in,
                              void* d_out, int out_size) {
    const float* x     = (const float*)d_in[0];
    const int*   ei    = (const int*)d_in[1];
    const float* W     = (const float*)d_in[2];
    const float* att_s = (const float*)d_in[3];
    const float* att_d = (const float*)d_in[4];
    const float* bias  = (const float*)d_in[5];
    const float* gamma = (const float*)d_in[6];
    const float* beta  = (const float*)d_in[7];
    float*       out   = (float*)d_out;

    k_init<<<(NN + 255) / 256, 256>>>();
    k_hist<<<(EE + 255) / 256, 256>>>(ei);
    k_scan<<<1, 1024>>>();
    dim3 gg((NN + BM - 1) / BM, HC / BN);
    k_gemm<<<gg, 256>>>(x, W, att_s, att_d);
    k_scatter<<<(ET + 255) / 256, 256>>>(ei);
    k_agg<<<(NN + 7) / 8, 256>>>(bias, gamma, beta, out);
}

// round 5
// speedup vs baseline: 1.5576x; 1.0340x over previous
#include <cuda_runtime.h>
#include <cuda_bf16.h>

// Problem constants (fixed by the dataset)
#define NN      50000
#define EE      800000
#define ET      850000          // EE + NN self loops
#define IN_CH   128
#define HC      256
#define HEADS   4
#define NEG_SLOPE 0.2f
#define LN_EPS  1e-5f

// packed fp32x2 helpers (FFMA2 path — 2x fp32 throughput on sm_103a)
#define FMA2(d, a, b, c) \
    asm("fma.rn.f32x2 %0, %1, %2, %3;" : "=l"(d) : "l"(a), "l"(b), "l"(c))
#define PACK2(d, x, y) \
    asm("mov.b64 %0, {%1, %2};" : "=l"(d) : "r"(__float_as_uint(x)), "r"(__float_as_uint(y)))
#define UNPACK2(x, y, d) \
    asm("mov.b64 {%0, %1}, %2;" : "=r"(x), "=r"(y) : "l"(d))

// ---------------- device scratch (static, no runtime alloc) ----------------
__device__ float g_h[(size_t)NN * HC];       // 51.2 MB  h = x@W
__device__ float g_as[NN * HEADS];           // per-node att_src dot
__device__ float g_ad[NN * HEADS];           // per-node att_dst dot
__device__ int   g_deg[NN];
__device__ int   g_off[NN + 1];
__device__ int   g_cur[NN];
__device__ int   g_src[ET];                  // sorted-by-dst source node ids

// ---------------- K1: init degree = 1 (self loop) ----------------
__global__ void k_init() {
    int i = blockIdx.x * blockDim.x + threadIdx.x;
    if (i < NN) g_deg[i] = 1;
}

// ---------------- K2: histogram of dst ----------------
__global__ void k_hist(const int* __restrict__ ei) {
    int i = blockIdx.x * blockDim.x + threadIdx.x;
    if (i < EE) {
        int dst = ei[EE + i];
        if (dst >= 0 && dst < NN) atomicAdd(&g_deg[dst], 1);
    }
}

// ---------------- K3: single-block exclusive scan ----------------
__global__ void k_scan() {
    __shared__ int s[1024];
    const int CH = (NN + 1023) / 1024;   // 49
    int t = threadIdx.x;
    int base = t * CH;
    int sum = 0;
    for (int j = 0; j < CH; j++) {
        int i = base + j;
        if (i < NN) sum += g_deg[i];
    }
    s[t] = sum;
    __syncthreads();
    for (int o = 1; o < 1024; o <<= 1) {
        int v = (t >= o) ? s[t - o] : 0;
        __syncthreads();
        s[t] += v;
        __syncthreads();
    }
    int run = (t == 0) ? 0 : s[t - 1];
    for (int j = 0; j < CH; j++) {
        int i = base + j;
        if (i < NN) {
            g_off[i] = run;
            g_cur[i] = run;
            run += g_deg[i];
        }
    }
    if (t == 0) g_off[NN] = s[1023];
}

// ---------------- K4: GEMM h = x@W (row-pair FFMA2, double-buffered) --------
// 64x128 block tile, BK=16, 256 threads; micro tile = 4 row-pairs x 4 cols.
#define BM 64
#define BN 128
#define BK 16
#define APITCH 68

__global__ __launch_bounds__(256) void k_gemm(const float* __restrict__ x,
                                              const float* __restrict__ W,
                                              const float* __restrict__ att_s,
                                              const float* __restrict__ att_d) {
    __shared__ float As[2][BK * APITCH];   // transposed: As[k][row]
    __shared__ float Bs[2][BK * BN];       // Bs[k][col]
    int t  = threadIdx.x;
    int bm = blockIdx.x * BM;
    int bn = blockIdx.y * BN;
    int tx = t & 31;          // col group (cols bn + tx*4 .. +3)
    int ty = t >> 5;          // row group (rows ty*8 .. ty*8+7)
    int lr = t >> 2;          // A-load row 0..63
    int lk = (t & 3) * 4;     // A-load k offset
    int wr = t >> 5;          // B-load k row 0..7
    int wc = (t & 31) * 4;    // B-load col

    unsigned long long acc[4][4] = {};     // [row-pair][col], packed fp32

    // preload tile 0
    {
        float4 av = make_float4(0.f, 0.f, 0.f, 0.f);
        int row = bm + lr;
        if (row < NN) av = *(const float4*)(x + (size_t)row * IN_CH + lk);
        As[0][(lk + 0) * APITCH + lr] = av.x;
        As[0][(lk + 1) * APITCH + lr] = av.y;
        As[0][(lk + 2) * APITCH + lr] = av.z;
        As[0][(lk + 3) * APITCH + lr] = av.w;
        *(float4*)(Bs[0] + wr * BN + wc) =
            *(const float4*)(W + (size_t)wr * HC + bn + wc);
        *(float4*)(Bs[0] + (wr + 8) * BN + wc) =
            *(const float4*)(W + (size_t)(wr + 8) * HC + bn + wc);
    }
    __syncthreads();

    int buf = 0;
    #pragma unroll
    for (int t8 = 0; t8 < 8; t8++) {
        float4 av, bv0, bv1;
        if (t8 < 7) {
            int kk = (t8 + 1) * BK;
            av = make_float4(0.f, 0.f, 0.f, 0.f);
            int row = bm + lr;
            if (row < NN) av = *(const float4*)(x + (size_t)row * IN_CH + kk + lk);
            bv0 = *(const float4*)(W + (size_t)(kk + wr) * HC + bn + wc);
            bv1 = *(const float4*)(W + (size_t)(kk + wr + 8) * HC + bn + wc);
        }
        const float* Ab = As[buf];
        const float* Bb = Bs[buf];
        #pragma unroll
        for (int k = 0; k < BK; k++) {
            unsigned long long a0 = *(const unsigned long long*)(Ab + k * APITCH + ty * 8);
            unsigned long long a1 = *(const unsigned long long*)(Ab + k * APITCH + ty * 8 + 2);
            unsigned long long a2 = *(const unsigned long long*)(Ab + k * APITCH + ty * 8 + 4);
            unsigned long long a3 = *(const unsigned long long*)(Ab + k * APITCH + ty * 8 + 6);
            float4 b = *(const float4*)(Bb + k * BN + tx * 4);
            unsigned long long bb0, bb1, bb2, bb3;
            PACK2(bb0, b.x, b.x);
            PACK2(bb1, b.y, b.y);
            PACK2(bb2, b.z, b.z);
            PACK2(bb3, b.w, b.w);
            FMA2(acc[0][0], a0, bb0, acc[0][0]);
            FMA2(acc[0][1], a0, bb1, acc[0][1]);
            FMA2(acc[0][2], a0, bb2, acc[0][2]);
            FMA2(acc[0][3], a0, bb3, acc[0][3]);
            FMA2(acc[1][0], a1, bb0, acc[1][0]);
            FMA2(acc[1][1], a1, bb1, acc[1][1]);
            FMA2(acc[1][2], a1, bb2, acc[1][2]);
            FMA2(acc[1][3], a1, bb3, acc[1][3]);
            FMA2(acc[2][0], a2, bb0, acc[2][0]);
            FMA2(acc[2][1], a2, bb1, acc[2][1]);
            FMA2(acc[2][2], a2, bb2, acc[2][2]);
            FMA2(acc[2][3], a2, bb3, acc[2][3]);
            FMA2(acc[3][0], a3, bb0, acc[3][0]);
            FMA2(acc[3][1], a3, bb1, acc[3][1]);
            FMA2(acc[3][2], a3, bb2, acc[3][2]);
            FMA2(acc[3][3], a3, bb3, acc[3][3]);
        }
        if (t8 < 7) {
            int nb = buf ^ 1;
            As[nb][(lk + 0) * APITCH + lr] = av.x;
            As[nb][(lk + 1) * APITCH + lr] = av.y;
            As[nb][(lk + 2) * APITCH + lr] = av.z;
            As[nb][(lk + 3) * APITCH + lr] = av.w;
            *(float4*)(Bs[nb] + wr * BN + wc) = bv0;
            *(float4*)(Bs[nb] + (wr + 8) * BN + wc) = bv1;
            __syncthreads();
            buf = nb;
        }
    }

    // epilogue: unpack row-pairs, store h, fused attention dots
    int head = (bn >> 6) + (tx >> 4);          // 64 cols per head
    int coff = (tx & 15) * 4;                  // channel offset within head
    float4 sa = *(const float4*)(att_s + head * 64 + coff);
    float4 da = *(const float4*)(att_d + head * 64 + coff);

    #pragma unroll
    for (int p = 0; p < 4; p++) {
        unsigned int l0, h0, l1, h1, l2, h2, l3, h3;
        UNPACK2(l0, h0, acc[p][0]);
        UNPACK2(l1, h1, acc[p][1]);
        UNPACK2(l2, h2, acc[p][2]);
        UNPACK2(l3, h3, acc[p][3]);
        float4 c0 = make_float4(__uint_as_float(l0), __uint_as_float(l1),
                                __uint_as_float(l2), __uint_as_float(l3));
        float4 c1 = make_float4(__uint_as_float(h0), __uint_as_float(h1),
                                __uint_as_float(h2), __uint_as_float(h3));
        int row0 = bm + ty * 8 + 2 * p;
        #pragma unroll
        for (int r = 0; r < 2; r++) {
            float4 c = r ? c1 : c0;
            int row = row0 + r;
            if (row < NN)
                *(float4*)(g_h + (size_t)row * HC + bn + tx * 4) = c;
            float ps = c.x * sa.x + c.y * sa.y + c.z * sa.z + c.w * sa.w;
            float pd = c.x * da.x + c.y * da.y + c.z * da.z + c.w * da.w;
            #pragma unroll
            for (int o = 1; o < 16; o <<= 1) {
                ps += __shfl_xor_sync(0xffffffffu, ps, o);
                pd += __shfl_xor_sync(0xffffffffu, pd, o);
            }
            if ((tx & 15) == 0 && row < NN) {
                g_as[row * HEADS + head] = ps;
                g_ad[row * HEADS + head] = pd;
            }
        }
    }
}

// ---------------- K6: counting-sort scatter (src permutation only) ----------
__global__ void k_scatter(const int* __restrict__ ei) {
    int i = blockIdx.x * blockDim.x + threadIdx.x;
    if (i >= ET) return;
    int src, dst;
    if (i < EE) { src = ei[i]; dst = ei[EE + i]; }
    else        { src = dst = i - EE; }
    if (src < 0 || src >= NN || dst < 0 || dst >= NN) return;
    int pos = atomicAdd(&g_cur[dst], 1);
    g_src[pos] = src;
}

// ---------------- K7: warp-per-node softmax-aggregate + LN + ELU ------------
// lane owns 8 channels (head = lane>>3). Logits computed inline from g_as/g_ad.
__global__ __launch_bounds__(256) void k_agg(const float* __restrict__ bias,
                                             const float* __restrict__ gamma,
                                             const float* __restrict__ beta,
                                             float* __restrict__ out) {
    int lane = threadIdx.x & 31;
    int n = blockIdx.x * 8 + (threadIdx.x >> 5);
    if (n >= NN) return;
    int start = g_off[n];
    int end   = g_off[n + 1];
    int head  = lane >> 3;
    int cb    = lane * 8;                    // first channel this lane owns
    float ad  = g_ad[n * HEADS + head];      // dst half, fixed per node/head

    float4 acc0 = make_float4(0.f, 0.f, 0.f, 0.f);
    float4 acc1 = make_float4(0.f, 0.f, 0.f, 0.f);
    float wsum = 0.f;

    for (int c = start; c < end; c += 32) {
        int sv = 0;
        if (c + lane < end) sv = g_src[c + lane];
        int cn = min(32, end - c);
        #pragma unroll 4
        for (int j = 0; j < cn; j++) {
            int src = __shfl_sync(0xffffffffu, sv, j);
            float v = g_as[src * HEADS + head] + ad;
            v = v > 0.f ? v : NEG_SLOPE * v;
            float w = __expf(v);
            wsum += w;
            const float4* hp = (const float4*)(g_h + (size_t)src * HC + cb);
            float4 h0 = hp[0], h1 = hp[1];
            acc0.x += w * h0.x; acc0.y += w * h0.y;
            acc0.z += w * h0.z; acc0.w += w * h0.w;
            acc1.x += w * h1.x; acc1.y += w * h1.y;
            acc1.z += w * h1.z; acc1.w += w * h1.w;
        }
    }

    float inv = 1.f / (wsum + 1e-16f);
    float4 b0 = ((const float4*)bias)[lane * 2];
    float4 b1 = ((const float4*)bias)[lane * 2 + 1];
    acc0.x = acc0.x * inv + b0.x; acc0.y = acc0.y * inv + b0.y;
    acc0.z = acc0.z * inv + b0.z; acc0.w = acc0.w * inv + b0.w;
    acc1.x = acc1.x * inv + b1.x; acc1.y = acc1.y * inv + b1.y;
    acc1.z = acc1.z * inv + b1.z; acc1.w = acc1.w * inv + b1.w;

    // LayerNorm over all 256 channels (warp reduce)
    float ss  = acc0.x + acc0.y + acc0.z + acc0.w + acc1.x + acc1.y + acc1.z + acc1.w;
    float ss2 = acc0.x * acc0.x + acc0.y * acc0.y + acc0.z * acc0.z + acc0.w * acc0.w
              + acc1.x * acc1.x + acc1.y * acc1.y + acc1.z * acc1.z + acc1.w * acc1.w;
    #pragma unroll
    for (int o = 16; o; o >>= 1) {
        ss  += __shfl_xor_sync(0xffffffffu, ss,  o);
        ss2 += __shfl_xor_sync(0xffffffffu, ss2, o);
    }
    float mu  = ss * (1.f / (float)HC);
    float var = ss2 * (1.f / (float)HC) - mu * mu;
    float r = rsqrtf(var + LN_EPS);

    float4 g0 = ((const float4*)gamma)[lane * 2];
    float4 g1 = ((const float4*)gamma)[lane * 2 + 1];
    float4 e0 = ((const float4*)beta)[lane * 2];
    float4 e1 = ((const float4*)beta)[lane * 2 + 1];
    float4 o0, o1;
    o0.x = (acc0.x - mu) * r * g0.x + e0.x;
    o0.y = (acc0.y - mu) * r * g0.y + e0.y;
    o0.z = (acc0.z - mu) * r * g0.z + e0.z;
    o0.w = (acc0.w - mu) * r * g0.w + e0.w;
    o1.x = (acc1.x - mu) * r * g1.x + e1.x;
    o1.y = (acc1.y - mu) * r * g1.y + e1.y;
    o1.z = (acc1.z - mu) * r * g1.z + e1.z;
    o1.w = (acc1.w - mu) * r * g1.w + e1.w;
    o0.x = o0.x > 0.f ? o0.x : (__expf(o0.x) - 1.f);
    o0.y = o0.y > 0.f ? o0.y : (__expf(o0.y) - 1.f);
    o0.z = o0.z > 0.f ? o0.z : (__expf(o0.z) - 1.f);
    o0.w = o0.w > 0.f ? o0.w : (__expf(o0.w) - 1.f);
    o1.x = o1.x > 0.f ? o1.x : (__expf(o1.x) - 1.f);
    o1.y = o1.y > 0.f ? o1.y : (__expf(o1.y) - 1.f);
    o1.z = o1.z > 0.f ? o1.z : (__expf(o1.z) - 1.f);
    o1.w = o1.w > 0.f ? o1.w : (__expf(o1.w) - 1.f);
    ((float4*)out)[(size_t)n * 64 + lane * 2]     = o0;
    ((float4*)out)[(size_t)n * 64 + lane * 2 + 1] = o1;
}

// ---------------- launch ----------------
extern "C" void kernel_launch(void* const* d_in, const int* in_sizes, int n_in,
                              void* d_out, int out_size) {
    const float* x     = (const float*)d_in[0];
    const int*   ei    = (const int*)d_in[1];
    const float* W     = (const float*)d_in[2];
    const float* att_s = (const float*)d_in[3];
    const float* att_d = (const float*)d_in[4];
    const float* bias  = (const float*)d_in[5];
    const float* gamma = (const float*)d_in[6];
    const float* beta  = (const float*)d_in[7];
    float*       out   = (float*)d_out;

    k_init<<<(NN + 255) / 256, 256>>>();
    k_hist<<<(EE + 255) / 256, 256>>>(ei);
    k_scan<<<1, 1024>>>();
    dim3 gg((NN + BM - 1) / BM, HC / BN);
    k_gemm<<<gg, 256>>>(x, W, att_s, att_d);
    k_scatter<<<(ET + 255) / 256, 256>>>(ei);
    k_agg<<<(NN + 7) / 8, 256>>>(bias, gamma, beta, out);
}